// round 16
// baseline (speedup 1.0000x reference)
#include <cuda_runtime.h>
#include <cuda_fp16.h>
#include <math.h>
#include <cstdint>

#define BB   2
#define HH   96
#define WW   96
#define PIX  (HH*WW)        // 9216
#define CINX 2048
#define CIX  512
#define CQKX 64
#define NCL  19

// ---------------- scratch (static device globals; no allocation) ------------
__device__ float g_A  [BB*CIX*PIX];
__device__ float g_Bf [BB*CIX*PIX];
__device__ float g_V  [BB*CIX*PIX];
__device__ float g_Q  [BB*CQKX*PIX];
__device__ float g_K  [BB*CQKX*PIX];
__device__ float g_Att[BB*PIX*192];
// pre-split weights (hi f16 | lo f16 << 16), same linear layout as fp32 weights
__device__ uint32_t g_Wa[CIX * CINX * 9];
__device__ uint32_t g_Wb[CIX * CIX * 9];
__device__ uint32_t g_Wt[CIX * (CINX + CIX) * 9];

// ---------------- fp16 split helpers -----------------------------------------
__device__ __forceinline__ uint32_t packsplit(float x) {
    __half h = __float2half_rn(x);
    __half l = __float2half_rn(x - __half2float(h));
    return (uint32_t)__half_as_ushort(h) | ((uint32_t)__half_as_ushort(l) << 16);
}

__global__ void __launch_bounds__(256)
prep_w_kernel(const float* __restrict__ w, uint32_t* __restrict__ o, int n)
{
    int i = blockIdx.x * 256 + threadIdx.x;
    if (i < n) o[i] = packsplit(w[i]);
}

// m16n8k16 f16 MMA
#define MMA_F16(d, a, b0, b1)                                                   \
    asm volatile("mma.sync.aligned.m16n8k16.row.col.f32.f16.f16.f32 "           \
        "{%0,%1,%2,%3}, {%4,%5,%6,%7}, {%8,%9}, {%0,%1,%2,%3};"                  \
        : "+f"((d)[0]), "+f"((d)[1]), "+f"((d)[2]), "+f"((d)[3])                 \
        : "r"((a)[0]), "r"((a)[1]), "r"((a)[2]), "r"((a)[3]),                    \
          "r"(b0), "r"(b1))

#define LDSM_X4(R0, R1, R2, R3, A)                                              \
    asm volatile("ldmatrix.sync.aligned.m8n8.x4.shared.b16 {%0,%1,%2,%3}, [%4];" \
        : "=r"(R0), "=r"(R1), "=r"(R2), "=r"(R3) : "r"(A))

__device__ __forceinline__ uint32_t smem_u32(const void* p) {
    uint32_t a;
    asm("{ .reg .u64 t; cvta.to.shared.u64 t, %1; cvt.u32.u64 %0, t; }"
        : "=r"(a) : "l"(p));
    return a;
}

// ============ fp16-split mma.sync implicit-GEMM 3x3 conv (ldmatrix) ==========
#define PADK   20
#define TILEU  2560
#define TILEB  10240
#define CSM_PATCH 0                       // 32x10x18 packed u32 = 23040 B
#define CSM_TILES 23040                   // AH0 AH1 AL0 AL1 BH0 BH1 BL0 BL1
#define CSM_TOTAL (23040 + 8*TILEB)       // 104960 B

// im2col build for one chunk, KB compile-time.
template<int KB>
__device__ __forceinline__ void build_b(const uint32_t* __restrict__ sPatch,
                                        uint32_t* __restrict__ sBh,
                                        uint32_t* __restrict__ sBl,
                                        int tid, int px_b, int kp_b, int pb)
{
    uint32_t hb[8], lb[8];
    const int kbase = KB + ((tid & 1) ? 16 : 0);
#pragma unroll
    for (int jp = 0; jp < 8; ++jp) {
        const int k0 = kbase + 2 * jp, k1 = k0 + 1;
        const int cl0 = k0 / 9, tp0 = k0 - cl0 * 9;
        const int cl1 = k1 / 9, tp1 = k1 - cl1 * 9;
        const int dy0 = tp0 / 3, dx0 = tp0 - dy0 * 3;
        const int dy1 = tp1 / 3, dx1 = tp1 - dy1 * 3;
        uint32_t w0 = sPatch[cl0 * 180 + dy0 * 18 + pb + dx0];
        uint32_t w1 = sPatch[cl1 * 180 + dy1 * 18 + pb + dx1];
        hb[jp] = __byte_perm(w0, w1, 0x5410);
        lb[jp] = __byte_perm(w0, w1, 0x7632);
    }
    uint32_t* dh = sBh + px_b * PADK + kp_b;
    uint32_t* dl = sBl + px_b * PADK + kp_b;
    *(uint4*)(dh)     = make_uint4(hb[0], hb[1], hb[2], hb[3]);
    *(uint4*)(dh + 4) = make_uint4(hb[4], hb[5], hb[6], hb[7]);
    *(uint4*)(dl)     = make_uint4(lb[0], lb[1], lb[2], lb[3]);
    *(uint4*)(dl + 4) = make_uint4(lb[4], lb[5], lb[6], lb[7]);
}

__device__ __forceinline__ void stage_a(const uint4* wpre,
                                        uint32_t* __restrict__ sAh,
                                        uint32_t* __restrict__ sAl,
                                        int coA, int j4A)
{
    const int d0 = coA * PADK + j4A * 2;
#pragma unroll
    for (int i = 0; i < 4; ++i) {
        const uint4 w = wpre[i];
        const int d = d0 + i * 32 * PADK;
        sAh[d]     = __byte_perm(w.x, w.y, 0x5410);
        sAh[d + 1] = __byte_perm(w.z, w.w, 0x5410);
        sAl[d]     = __byte_perm(w.x, w.y, 0x7632);
        sAl[d + 1] = __byte_perm(w.z, w.w, 0x7632);
    }
}

__global__ void __launch_bounds__(256, 2)
conv_tc_kernel(const float* __restrict__ in, const uint32_t* __restrict__ wgt,
               const float* __restrict__ scale, const float* __restrict__ bias,
               float* __restrict__ outp, int Cin, int WCin9, int coff9, int flags)
{
    extern __shared__ char smem[];
    uint32_t* sPatch = (uint32_t*)(smem + CSM_PATCH);
    const uint32_t sb = smem_u32(smem);

    const int tid  = threadIdx.x;
    const int lane = tid & 31;
    const int wid  = tid >> 5;
    const int g    = lane >> 2;
    const int tig  = lane & 3;
    const int mw   = (wid & 3) * 32;
    const int nw   = (wid >> 2) * 64;

    const int tile_w = blockIdx.x * 16;
    const int tile_h = blockIdx.y * 8;
    const int b      = blockIdx.z >> 2;
    const int co0    = (blockIdx.z & 3) * 128;

    float acc[2][8][4];
#pragma unroll
    for (int mi = 0; mi < 2; ++mi)
#pragma unroll
        for (int ni = 0; ni < 8; ++ni)
#pragma unroll
            for (int q = 0; q < 4; ++q) acc[mi][ni][q] = 0.f;

    const float* inb = in + (size_t)b * Cin * PIX;
    const int groups = Cin >> 5;
    const int nsteps = groups * 9;

    const int coA = tid >> 3;
    const int j4A = tid & 7;
    const uint32_t* wpA = wgt + coff9 + (size_t)(co0 + coA) * WCin9 + j4A * 4;

    const int px_b = tid >> 1;
    const int kp_b = (tid & 1) * 8;
    const int pb   = (px_b >> 4) * 18 + (px_b & 15);

    const int mm = lane >> 3, rr8 = lane & 7;
    const uint32_t aOff = (uint32_t)((mw + (mm & 1) * 8 + rr8) * 80 + (mm >> 1) * 16);
    const uint32_t bOff = (uint32_t)((nw + ((mm >> 1) & 1) * 8 + rr8) * 80 + (mm & 1) * 16);

    // patch stage helper (inline lambda-style macro)
#define STAGE_PATCH(GRP) do {                                                   \
        for (int idx = tid; idx < 32 * 180; idx += 256) {                       \
            int c = idx / 180, rem = idx % 180;                                 \
            int pr = rem / 18, pc = rem % 18;                                   \
            int gh = tile_h - 1 + pr, gw = tile_w - 1 + pc;                     \
            float v = 0.f;                                                      \
            if ((unsigned)gh < 96u && (unsigned)gw < 96u)                       \
                v = inb[(size_t)((GRP) * 32 + c) * PIX + gh * 96 + gw];         \
            sPatch[idx] = packsplit(v);                                         \
        }                                                                       \
    } while (0)

    // ---- prologue: patch(0), tiles(step 0), weights w(1) prefetched ----
    uint4 wpre[4];
#pragma unroll
    for (int i = 0; i < 4; ++i)
        wpre[i] = *(const uint4*)(wpA + (size_t)(32 * i) * WCin9);

    STAGE_PATCH(0);
    __syncthreads();
    {
        uint32_t* sAh = (uint32_t*)(smem + CSM_TILES);
        uint32_t* sAl = (uint32_t*)(smem + CSM_TILES + 2 * TILEB);
        uint32_t* sBh = (uint32_t*)(smem + CSM_TILES + 4 * TILEB);
        uint32_t* sBl = (uint32_t*)(smem + CSM_TILES + 6 * TILEB);
        stage_a(wpre, sAh, sAl, coA, j4A);
        build_b<0>(sPatch, sBh, sBl, tid, px_b, kp_b, pb);
        if (1 < nsteps) {
            const uint32_t* wp = wpA + 32;
#pragma unroll
            for (int i = 0; i < 4; ++i)
                wpre[i] = *(const uint4*)(wp + (size_t)(32 * i) * WCin9);
        }
    }
    __syncthreads();

    // ---- main loop: per epoch = MMA(cur) then stage(next), one sync ----
    int buf = 0;
    for (int grp = 0; grp < groups; ++grp) {
#pragma unroll
        for (int c9 = 0; c9 < 9; ++c9) {
            const int step = grp * 9 + c9;

            // MMA burst on tiles[buf]
            {
                const uint32_t tAh = sb + CSM_TILES + buf * TILEB;
                const uint32_t tAl = tAh + 2 * TILEB;
                const uint32_t tBh = tAh + 4 * TILEB;
                const uint32_t tBl = tAh + 6 * TILEB;
#pragma unroll
                for (int ks = 0; ks < 2; ++ks) {
                    const uint32_t kadd = ks * 32;
                    uint32_t ah[2][4], al[2][4];
                    LDSM_X4(ah[0][0], ah[0][1], ah[0][2], ah[0][3], tAh + aOff + kadd);
                    LDSM_X4(ah[1][0], ah[1][1], ah[1][2], ah[1][3], tAh + aOff + 1280 + kadd);
                    LDSM_X4(al[0][0], al[0][1], al[0][2], al[0][3], tAl + aOff + kadd);
                    LDSM_X4(al[1][0], al[1][1], al[1][2], al[1][3], tAl + aOff + 1280 + kadd);
#pragma unroll
                    for (int nip = 0; nip < 4; ++nip) {
                        uint32_t bh0, bh1, bh2, bh3, bl0, bl1, bl2, bl3;
                        LDSM_X4(bh0, bh1, bh2, bh3, tBh + bOff + nip * 1280 + kadd);
                        LDSM_X4(bl0, bl1, bl2, bl3, tBl + bOff + nip * 1280 + kadd);
                        const int ne = 2 * nip, no = 2 * nip + 1;
                        MMA_F16(acc[0][ne], ah[0], bh0, bh1);
                        MMA_F16(acc[1][ne], ah[1], bh0, bh1);
                        MMA_F16(acc[0][no], ah[0], bh2, bh3);
                        MMA_F16(acc[1][no], ah[1], bh2, bh3);
                        MMA_F16(acc[0][ne], ah[0], bl0, bl1);
                        MMA_F16(acc[1][ne], ah[1], bl0, bl1);
                        MMA_F16(acc[0][no], ah[0], bl2, bl3);
                        MMA_F16(acc[1][no], ah[1], bl2, bl3);
                        MMA_F16(acc[0][ne], al[0], bh0, bh1);
                        MMA_F16(acc[1][ne], al[1], bh0, bh1);
                        MMA_F16(acc[0][no], al[0], bh2, bh3);
                        MMA_F16(acc[1][no], al[1], bh2, bh3);
                    }
                }
            }

            // stage(next) into buf^1
            const int nxt = step + 1;
            uint32_t* nAh = (uint32_t*)(smem + CSM_TILES + (buf ^ 1) * TILEB);
            uint32_t* nAl = (uint32_t*)(smem + CSM_TILES + (2 + (buf ^ 1)) * TILEB);
            uint32_t* nBh = (uint32_t*)(smem + CSM_TILES + (4 + (buf ^ 1)) * TILEB);
            uint32_t* nBl = (uint32_t*)(smem + CSM_TILES + (6 + (buf ^ 1)) * TILEB);

            if (c9 == 8) {
                if (grp + 1 < groups) {
                    STAGE_PATCH(grp + 1);
                    __syncthreads();           // patch(grp+1) visible
                    stage_a(wpre, nAh, nAl, coA, j4A);
                    build_b<0>(sPatch, nBh, nBl, tid, px_b, kp_b, pb);
                    if (nxt + 1 < nsteps) {
                        const uint32_t* wp = wpA + (size_t)(nxt + 1) * 32;
#pragma unroll
                        for (int i = 0; i < 4; ++i)
                            wpre[i] = *(const uint4*)(wp + (size_t)(32 * i) * WCin9);
                    }
                    __syncthreads();           // tiles(nxt) ready
                }
            } else {
                stage_a(wpre, nAh, nAl, coA, j4A);
                switch (c9 + 1) {
                    case 1: build_b<32 >(sPatch, nBh, nBl, tid, px_b, kp_b, pb); break;
                    case 2: build_b<64 >(sPatch, nBh, nBl, tid, px_b, kp_b, pb); break;
                    case 3: build_b<96 >(sPatch, nBh, nBl, tid, px_b, kp_b, pb); break;
                    case 4: build_b<128>(sPatch, nBh, nBl, tid, px_b, kp_b, pb); break;
                    case 5: build_b<160>(sPatch, nBh, nBl, tid, px_b, kp_b, pb); break;
                    case 6: build_b<192>(sPatch, nBh, nBl, tid, px_b, kp_b, pb); break;
                    case 7: build_b<224>(sPatch, nBh, nBl, tid, px_b, kp_b, pb); break;
                    default: build_b<256>(sPatch, nBh, nBl, tid, px_b, kp_b, pb); break;
                }
                if (nxt + 1 < nsteps) {
                    const uint32_t* wp = wpA + (size_t)(nxt + 1) * 32;
#pragma unroll
                    for (int i = 0; i < 4; ++i)
                        wpre[i] = *(const uint4*)(wp + (size_t)(32 * i) * WCin9);
                }
                __syncthreads();               // tiles(nxt) ready
            }
            buf ^= 1;
        }
    }
#undef STAGE_PATCH

    // ---- epilogue: acc -> gmem (bn / relu / accumulate) ----
#pragma unroll
    for (int mi = 0; mi < 2; ++mi) {
#pragma unroll
        for (int rr = 0; rr < 2; ++rr) {
            int co = co0 + mw + mi * 16 + g + rr * 8;
            float s = 1.f, bs = 0.f;
            if (flags & 2) { s = scale[co]; bs = bias[co]; }
            const size_t obase = ((size_t)(b * 512 + co)) * PIX;
#pragma unroll
            for (int ni = 0; ni < 8; ++ni) {
#pragma unroll
                for (int cc = 0; cc < 2; ++cc) {
                    int px = nw + ni * 8 + 2 * tig + cc;
                    size_t oi = obase + (size_t)(tile_h + (px >> 4)) * 96
                              + tile_w + (px & 15);
                    float v = acc[mi][ni][rr * 2 + cc];
                    if (flags & 1) v += outp[oi];
                    v = v * s + bs;
                    if (flags & 4) v = fmaxf(v, 0.f);
                    outp[oi] = v;
                }
            }
        }
    }
}

// ---------------- fused q+k 1x1 projection (math identical to pw) ------------
__global__ void __launch_bounds__(256)
qk_kernel(const float* __restrict__ in, const float* __restrict__ qw,
          const float* __restrict__ kw, float* __restrict__ qo,
          float* __restrict__ ko)
{
    const int px0 = blockIdx.x * 128;
    const float* wgt = blockIdx.y ? kw : qw;
    float* out      = blockIdx.y ? ko : qo;
    const int b   = blockIdx.z;
    __shared__ float sIn[16][128];
    __shared__ float sW[64][17];
    const int tid = threadIdx.x, tx = tid & 15, ty = tid >> 4;
    float acc[4][8];
#pragma unroll
    for (int i = 0; i < 4; ++i)
#pragma unroll
        for (int r = 0; r < 8; ++r) acc[i][r] = 0.f;

    const float* inb = in + (size_t)b * CIX * PIX;
    for (int c0 = 0; c0 < CIX; c0 += 16) {
        __syncthreads();
#pragma unroll
        for (int k = 0; k < 8; ++k) {
            int idx = tid + k*256;
            sIn[idx >> 7][idx & 127] =
                inb[(size_t)(c0 + (idx >> 7)) * PIX + px0 + (idx & 127)];
        }
#pragma unroll
        for (int k = 0; k < 4; ++k) {
            int idx = tid + k*256;
            sW[idx >> 4][idx & 15] =
                wgt[(size_t)(idx >> 4) * CIX + c0 + (idx & 15)];
        }
        __syncthreads();
#pragma unroll
        for (int j = 0; j < 16; ++j) {
            float iv[8];
#pragma unroll
            for (int r = 0; r < 8; ++r) iv[r] = sIn[j][tx + 16*r];
#pragma unroll
            for (int i = 0; i < 4; ++i) {
                float wv = sW[ty*4 + i][j];
#pragma unroll
                for (int r = 0; r < 8; ++r)
                    acc[i][r] = fmaf(wv, iv[r], acc[i][r]);
            }
        }
    }
#pragma unroll
    for (int i = 0; i < 4; ++i)
#pragma unroll
        for (int r = 0; r < 8; ++r)
            out[((size_t)b*CQKX + ty*4 + i)*PIX + px0 + tx + 16*r] = acc[i][r];
}

// ---------------- v projection: 8co x 8px per thread (same k order) ----------
__global__ void __launch_bounds__(256)
pwv_kernel(const float* __restrict__ in, const float* __restrict__ wgt,
           float* __restrict__ out)
{
    const int px0 = blockIdx.x * 128;
    const int o0  = blockIdx.y * 128;
    const int b   = blockIdx.z;
    __shared__ float sIn[16][128];
    __shared__ float sW[128][17];
    const int tid = threadIdx.x, tx = tid & 15, ty = tid >> 4;
    float acc[8][8];
#pragma unroll
    for (int i = 0; i < 8; ++i)
#pragma unroll
        for (int r = 0; r < 8; ++r) acc[i][r] = 0.f;

    const float* inb = in + (size_t)b * CIX * PIX;
    for (int c0 = 0; c0 < CIX; c0 += 16) {
        __syncthreads();
#pragma unroll
        for (int k = 0; k < 8; ++k) {
            int idx = tid + k*256;
            sIn[idx >> 7][idx & 127] =
                inb[(size_t)(c0 + (idx >> 7)) * PIX + px0 + (idx & 127)];
        }
#pragma unroll
        for (int k = 0; k < 8; ++k) {
            int idx = tid + k*256;
            sW[idx >> 4][idx & 15] =
                wgt[(size_t)(o0 + (idx >> 4)) * CIX + c0 + (idx & 15)];
        }
        __syncthreads();
#pragma unroll
        for (int j = 0; j < 16; ++j) {
            float iv[8];
#pragma unroll
            for (int r = 0; r < 8; ++r) iv[r] = sIn[j][tx + 16*r];
#pragma unroll
            for (int i = 0; i < 8; ++i) {
                float wv = sW[ty*8 + i][j];
#pragma unroll
                for (int r = 0; r < 8; ++r)
                    acc[i][r] = fmaf(wv, iv[r], acc[i][r]);
            }
        }
    }
#pragma unroll
    for (int i = 0; i < 8; ++i)
#pragma unroll
        for (int r = 0; r < 8; ++r)
            out[((size_t)b*CIX + o0 + ty*8 + i)*PIX + px0 + tx + 16*r] = acc[i][r];
}

// ---------------- energies (unchanged) ---------------------------------------
__global__ void __launch_bounds__(256)
energyH_kernel(const float* __restrict__ q, const float* __restrict__ k,
               float* __restrict__ att)
{
    const int w = blockIdx.x, b = blockIdx.y;
    __shared__ float sQ[32][96], sK[32][96];
    const int tid = threadIdx.x;
    float acc[36];
#pragma unroll
    for (int i = 0; i < 36; ++i) acc[i] = 0.f;

    for (int c0 = 0; c0 < CQKX; c0 += 32) {
        __syncthreads();
        for (int idx = tid; idx < 32*96; idx += 256) {
            int c = idx / 96, p = idx % 96;
            size_t off = (size_t)(b*CQKX + c0 + c) * PIX + p*96 + w;
            sQ[c][p] = q[off];
            sK[c][p] = k[off];
        }
        __syncthreads();
#pragma unroll
        for (int it = 0; it < 36; ++it) {
            int oi = it*256 + tid;
            int h = oi / 96, gg = oi % 96;
            float s = acc[it];
#pragma unroll
            for (int c = 0; c < 32; ++c) s = fmaf(sQ[c][h], sK[c][gg], s);
            acc[it] = s;
        }
    }
#pragma unroll
    for (int it = 0; it < 36; ++it) {
        int oi = it*256 + tid;
        int h = oi / 96, gg = oi % 96;
        float vv = (gg == h) ? __int_as_float(0xff800000u) : acc[it];
        att[((size_t)((b*96 + h)*96 + w))*192 + gg] = vv;
    }
}

__global__ void __launch_bounds__(256)
energyW_kernel(const float* __restrict__ q, const float* __restrict__ k,
               float* __restrict__ att)
{
    const int h = blockIdx.x, b = blockIdx.y;
    __shared__ float sQ[32][96], sK[32][96];
    const int tid = threadIdx.x;
    float acc[36];
#pragma unroll
    for (int i = 0; i < 36; ++i) acc[i] = 0.f;

    for (int c0 = 0; c0 < CQKX; c0 += 32) {
        __syncthreads();
        for (int idx = tid; idx < 32*96; idx += 256) {
            int c = idx / 96, p = idx % 96;
            size_t off = (size_t)(b*CQKX + c0 + c) * PIX + h*96 + p;
            sQ[c][p] = q[off];
            sK[c][p] = k[off];
        }
        __syncthreads();
#pragma unroll
        for (int it = 0; it < 36; ++it) {
            int oi = it*256 + tid;
            int wc = oi / 96, v2 = oi % 96;
            float s = acc[it];
#pragma unroll
            for (int c = 0; c < 32; ++c) s = fmaf(sQ[c][wc], sK[c][v2], s);
            acc[it] = s;
        }
    }
#pragma unroll
    for (int it = 0; it < 36; ++it) {
        int oi = it*256 + tid;
        int wc = oi / 96, v2 = oi % 96;
        att[((size_t)((b*96 + h)*96 + wc))*192 + 96 + v2] = acc[it];
    }
}

// ---------------- softmax over 192 (unchanged) --------------------------------
__global__ void softmax_kernel(float* __restrict__ att)
{
    const int t = threadIdx.x;
    const size_t base = (size_t)blockIdx.x * 192;
    float v = att[base + t];
    __shared__ float red[6];

    float m = v;
#pragma unroll
    for (int o = 16; o; o >>= 1) m = fmaxf(m, __shfl_xor_sync(0xffffffffu, m, o));
    if ((t & 31) == 0) red[t >> 5] = m;
    __syncthreads();
    m = fmaxf(fmaxf(fmaxf(red[0], red[1]), fmaxf(red[2], red[3])),
              fmaxf(red[4], red[5]));

    float e = expf(v - m);
    float s = e;
#pragma unroll
    for (int o = 16; o; o >>= 1) s += __shfl_xor_sync(0xffffffffu, s, o);
    __syncthreads();
    if ((t & 31) == 0) red[t >> 5] = s;
    __syncthreads();
    s = red[0] + red[1] + red[2] + red[3] + red[4] + red[5];
    att[base + t] = e / s;
}

// ---------------- aggregation (unchanged) -------------------------------------
__global__ void __launch_bounds__(256)
aggH_kernel(const float* __restrict__ v, const float* __restrict__ att,
            const float* __restrict__ feat, const float* __restrict__ gp,
            float* __restrict__ dst)
{
    const int w = blockIdx.x, b = blockIdx.y;
    const int tid = threadIdx.x;
    __shared__ float sA2[96][97];
    __shared__ float sV[16][97];
    const float gm = *gp;

    for (int idx = tid; idx < 96*96; idx += 256) {
        int h = idx / 96, gg = idx % 96;
        sA2[h][gg] = att[((size_t)((b*96 + h)*96 + w))*192 + gg];
    }
    const int clg = tid >> 5;
    const int hq  = tid & 31;

    for (int c0 = 0; c0 < CIX; c0 += 16) {
        __syncthreads();
        for (int idx = tid; idx < 16*96; idx += 256) {
            int cl = idx / 96, gg = idx % 96;
            sV[cl][gg] = v[(size_t)(b*CIX + c0 + cl) * PIX + gg*96 + w];
        }
        __syncthreads();
        float a0[3] = {0.f,0.f,0.f}, a1[3] = {0.f,0.f,0.f};
#pragma unroll 4
        for (int gg = 0; gg < 96; ++gg) {
            float v0 = sV[clg*2][gg], v1 = sV[clg*2+1][gg];
#pragma unroll
            for (int r = 0; r < 3; ++r) {
                float a = sA2[hq + 32*r][gg];
                a0[r] = fmaf(v0, a, a0[r]);
                a1[r] = fmaf(v1, a, a1[r]);
            }
        }
#pragma unroll
        for (int r = 0; r < 3; ++r) {
            int h = hq + 32*r;
            size_t oi0 = ((size_t)(b*CIX + c0 + clg*2    )*96 + h)*96 + w;
            size_t oi1 = ((size_t)(b*CIX + c0 + clg*2 + 1)*96 + h)*96 + w;
            dst[oi0] = feat[oi0] + gm * a0[r];
            dst[oi1] = feat[oi1] + gm * a1[r];
        }
    }
}

__global__ void __launch_bounds__(256)
aggW_kernel(const float* __restrict__ v, const float* __restrict__ att,
            const float* __restrict__ gp, float* __restrict__ dst)
{
    const int h = blockIdx.x, b = blockIdx.y;
    const int tid = threadIdx.x;
    __shared__ float sA2[96][97];
    __shared__ float sV[16][97];
    const float gm = *gp;

    for (int idx = tid; idx < 96*96; idx += 256) {
        int wc = idx / 96, v2 = idx % 96;
        sA2[wc][v2] = att[((size_t)((b*96 + h)*96 + wc))*192 + 96 + v2];
    }
    const int clg = tid >> 5;
    const int wq  = tid & 31;

    for (int c0 = 0; c0 < CIX; c0 += 16) {
        __syncthreads();
        for (int idx = tid; idx < 16*96; idx += 256) {
            int cl = idx / 96, v2 = idx % 96;
            sV[cl][v2] = v[(size_t)(b*CIX + c0 + cl) * PIX + h*96 + v2];
        }
        __syncthreads();
        float a0[3] = {0.f,0.f,0.f}, a1[3] = {0.f,0.f,0.f};
#pragma unroll 4
        for (int v2 = 0; v2 < 96; ++v2) {
            float v0 = sV[clg*2][v2], v1 = sV[clg*2+1][v2];
#pragma unroll
            for (int r = 0; r < 3; ++r) {
                float a = sA2[wq + 32*r][v2];
                a0[r] = fmaf(v0, a, a0[r]);
                a1[r] = fmaf(v1, a, a1[r]);
            }
        }
#pragma unroll
        for (int r = 0; r < 3; ++r) {
            int wc = wq + 32*r;
            size_t oi0 = ((size_t)(b*CIX + c0 + clg*2    )*96 + h)*96 + wc;
            size_t oi1 = ((size_t)(b*CIX + c0 + clg*2 + 1)*96 + h)*96 + wc;
            dst[oi0] += gm * a0[r];
            dst[oi1] += gm * a1[r];
        }
    }
}

// ---------------- final 1x1 (unchanged) ---------------------------------------
__global__ void __launch_bounds__(256)
final_kernel(const float* __restrict__ in, const float* __restrict__ ow,
             const float* __restrict__ ob, float* __restrict__ out)
{
    const int px0 = blockIdx.x * 256;
    const int b   = blockIdx.y;
    const int tid = threadIdx.x;
    __shared__ float sIn[32][256];
    __shared__ float sW[19][32];
    float acc[NCL];
#pragma unroll
    for (int o = 0; o < NCL; ++o) acc[o] = 0.f;

    for (int c0 = 0; c0 < CIX; c0 += 32) {
        __syncthreads();
#pragma unroll
        for (int k = 0; k < 32; ++k)
            sIn[k][tid] = in[(size_t)(b*CIX + c0 + k) * PIX + px0 + tid];
        for (int idx = tid; idx < NCL*32; idx += 256)
            sW[idx >> 5][idx & 31] = ow[(size_t)(idx >> 5) * CIX + c0 + (idx & 31)];
        __syncthreads();
#pragma unroll
        for (int j = 0; j < 32; ++j) {
            float xv = sIn[j][tid];
#pragma unroll
            for (int o = 0; o < NCL; ++o) acc[o] = fmaf(sW[o][j], xv, acc[o]);
        }
    }
#pragma unroll
    for (int o = 0; o < NCL; ++o)
        out[((size_t)(b*NCL + o)) * PIX + px0 + tid] = acc[o] + ob[o];
}

// ---------------- launcher -----------------------------------------------------
extern "C" void kernel_launch(void* const* d_in, const int* in_sizes, int n_in,
                              void* d_out, int out_size)
{
    const float* x       = (const float*)d_in[0];
    const float* conva_w = (const float*)d_in[1];
    const float* bn1_s   = (const float*)d_in[2];
    const float* bn1_b   = (const float*)d_in[3];
    const float* q_w     = (const float*)d_in[4];
    const float* k_w     = (const float*)d_in[5];
    const float* v_w     = (const float*)d_in[6];
    const float* gamma   = (const float*)d_in[7];
    const float* convb_w = (const float*)d_in[8];
    const float* bn2_s   = (const float*)d_in[9];
    const float* bn2_b   = (const float*)d_in[10];
    const float* bott_w  = (const float*)d_in[11];
    const float* bn3_s   = (const float*)d_in[12];
    const float* bn3_b   = (const float*)d_in[13];
    const float* out_w   = (const float*)d_in[14];
    const float* out_b   = (const float*)d_in[15];
    float* out = (float*)d_out;

    float *pA, *pB, *pV, *pQ, *pK, *pAtt;
    uint32_t *pWa, *pWb, *pWt;
    cudaGetSymbolAddress((void**)&pA,   g_A);
    cudaGetSymbolAddress((void**)&pB,   g_Bf);
    cudaGetSymbolAddress((void**)&pV,   g_V);
    cudaGetSymbolAddress((void**)&pQ,   g_Q);
    cudaGetSymbolAddress((void**)&pK,   g_K);
    cudaGetSymbolAddress((void**)&pAtt, g_Att);
    cudaGetSymbolAddress((void**)&pWa,  g_Wa);
    cudaGetSymbolAddress((void**)&pWb,  g_Wb);
    cudaGetSymbolAddress((void**)&pWt,  g_Wt);

    cudaFuncSetAttribute(conv_tc_kernel,
                         cudaFuncAttributeMaxDynamicSharedMemorySize, CSM_TOTAL);

    const int nWa = CIX * CINX * 9;
    const int nWb = CIX * CIX * 9;
    const int nWt = CIX * (CINX + CIX) * 9;
    prep_w_kernel<<<(nWa + 255)/256, 256>>>(conva_w, pWa, nWa);
    prep_w_kernel<<<(nWb + 255)/256, 256>>>(convb_w, pWb, nWb);
    prep_w_kernel<<<(nWt + 255)/256, 256>>>(bott_w,  pWt, nWt);

    dim3 cgrid(6, 12, BB * (CIX/128));

    // conva + bn1 + relu -> A
    conv_tc_kernel<<<cgrid, 256, CSM_TOTAL>>>(x, pWa, bn1_s, bn1_b, pA,
                                              CINX, CINX*9, 0, 2|4);

    // 2 recurrences of criss-cross attention (fp32, proven)
    for (int r = 0; r < 2; ++r) {
        const float* feat = r ? pB : pA;
        float*       dst  = r ? pA : pB;
        qk_kernel<<<dim3(72, 2, BB), 256>>>(feat, q_w, k_w, pQ, pK);
        pwv_kernel<<<dim3(72, 4, BB), 256>>>(feat, v_w, pV);
        energyH_kernel<<<dim3(96, BB), 256>>>(pQ, pK, pAtt);
        energyW_kernel<<<dim3(96, BB), 256>>>(pQ, pK, pAtt);
        softmax_kernel<<<BB*PIX, 192>>>(pAtt);
        aggH_kernel<<<dim3(96, BB), 256>>>(pV, pAtt, feat, gamma, dst);
        aggW_kernel<<<dim3(96, BB), 256>>>(pV, pAtt, gamma, dst);
    }

    // convb + bn2 + relu : A -> B
    conv_tc_kernel<<<cgrid, 256, CSM_TOTAL>>>(pA, pWb, bn2_s, bn2_b, pB,
                                              CIX, CIX*9, 0, 2|4);

    // bottleneck conv over virtual concat [x (2048ch), B (512ch)] -> V, bn3
    conv_tc_kernel<<<cgrid, 256, CSM_TOTAL>>>(x,  pWt, nullptr, nullptr, pV,
                                              CINX, (CINX+CIX)*9, 0, 0);
    conv_tc_kernel<<<cgrid, 256, CSM_TOTAL>>>(pB, pWt, bn3_s, bn3_b, pV,
                                              CIX, (CINX+CIX)*9, CINX*9, 1|2);

    // final 1x1 -> d_out
    final_kernel<<<dim3(PIX/256, BB), 256>>>(pV, out_w, out_b, out);
}

// round 17
// speedup vs baseline: 1.1213x; 1.1213x over previous
#include <cuda_runtime.h>
#include <cuda_fp16.h>
#include <math.h>
#include <cstdint>

#define BB   2
#define HH   96
#define WW   96
#define PIX  (HH*WW)        // 9216
#define CINX 2048
#define CIX  512
#define CQKX 64
#define NCL  19

// ---------------- scratch (static device globals; no allocation) ------------
__device__ float g_A  [BB*CIX*PIX];
__device__ float g_Bf [BB*CIX*PIX];
__device__ float g_V  [BB*CIX*PIX];
__device__ float g_Q  [BB*CQKX*PIX];
__device__ float g_K  [BB*CQKX*PIX];
__device__ float g_Att[BB*PIX*192];
// pre-split weights (hi f16 | lo f16 << 16), same linear layout as fp32 weights
__device__ uint32_t g_Wa[CIX * CINX * 9];
__device__ uint32_t g_Wb[CIX * CIX * 9];
__device__ uint32_t g_Wt[CIX * (CINX + CIX) * 9];

// ---------------- fp16 split helpers -----------------------------------------
__device__ __forceinline__ uint32_t packsplit(float x) {
    __half h = __float2half_rn(x);
    __half l = __float2half_rn(x - __half2float(h));
    return (uint32_t)__half_as_ushort(h) | ((uint32_t)__half_as_ushort(l) << 16);
}

__global__ void __launch_bounds__(256)
prep_w_kernel(const float* __restrict__ w, uint32_t* __restrict__ o, int n)
{
    int i = blockIdx.x * 256 + threadIdx.x;
    if (i < n) o[i] = packsplit(w[i]);
}

// m16n8k16 f16 MMA
#define MMA_F16(d, a, b0, b1)                                                   \
    asm volatile("mma.sync.aligned.m16n8k16.row.col.f32.f16.f16.f32 "           \
        "{%0,%1,%2,%3}, {%4,%5,%6,%7}, {%8,%9}, {%0,%1,%2,%3};"                  \
        : "+f"((d)[0]), "+f"((d)[1]), "+f"((d)[2]), "+f"((d)[3])                 \
        : "r"((a)[0]), "r"((a)[1]), "r"((a)[2]), "r"((a)[3]),                    \
          "r"(b0), "r"(b1))

#define LDSM_X4(R0, R1, R2, R3, A)                                              \
    asm volatile("ldmatrix.sync.aligned.m8n8.x4.shared.b16 {%0,%1,%2,%3}, [%4];" \
        : "=r"(R0), "=r"(R1), "=r"(R2), "=r"(R3) : "r"(A))

__device__ __forceinline__ uint32_t smem_u32(const void* p) {
    uint32_t a;
    asm("{ .reg .u64 t; cvta.to.shared.u64 t, %1; cvt.u32.u64 %0, t; }"
        : "=r"(a) : "l"(p));
    return a;
}

// ============ fp16-split mma.sync implicit-GEMM 3x3 conv (ldmatrix) ==========
// EXACT R15 version (proven 10.0 ms / tensor 57.7%) — do not perturb.
#define PADK   20
#define TILEU  2560                       // u32 per tile
#define TILEB  10240                      // bytes per tile
#define CSM_PATCH 0                       // 32x10x18 packed u32 = 23040 B
#define CSM_TILES 23040                   // AH0 AH1 AL0 AL1 BH0 BH1 BL0 BL1
#define CSM_TOTAL (23040 + 8*TILEB)       // 104960 B

#define BUILD_B_HALF(KB) do {                                                   \
    _Pragma("unroll")                                                           \
    for (int jp = 0; jp < 8; ++jp) {                                            \
        const int k0 = (KB) + 2*jp, k1 = k0 + 1;                                \
        const int cl0 = k0/9, tp0 = k0 - cl0*9;                                 \
        const int cl1 = k1/9, tp1 = k1 - cl1*9;                                 \
        const int dy0 = tp0/3, dx0 = tp0 - dy0*3;                               \
        const int dy1 = tp1/3, dx1 = tp1 - dy1*3;                               \
        uint32_t w0 = sPatch[cl0*180 + dy0*18 + pb + dx0];                      \
        uint32_t w1 = sPatch[cl1*180 + dy1*18 + pb + dx1];                      \
        hb[jp] = __byte_perm(w0, w1, 0x5410);                                   \
        lb[jp] = __byte_perm(w0, w1, 0x7632);                                   \
    }                                                                           \
} while (0)

__global__ void __launch_bounds__(256, 2)
conv_tc_kernel(const float* __restrict__ in, const uint32_t* __restrict__ wgt,
               const float* __restrict__ scale, const float* __restrict__ bias,
               float* __restrict__ outp, int Cin, int WCin9, int coff9, int flags)
{
    extern __shared__ char smem[];
    uint32_t* sPatch = (uint32_t*)(smem + CSM_PATCH);
    const uint32_t sb = smem_u32(smem);

    const int tid  = threadIdx.x;
    const int lane = tid & 31;
    const int wid  = tid >> 5;
    const int g    = lane >> 2;
    const int tig  = lane & 3;
    const int mw   = (wid & 3) * 32;     // warp co offset
    const int nw   = (wid >> 2) * 64;    // warp px offset

    const int tile_w = blockIdx.x * 16;
    const int tile_h = blockIdx.y * 8;
    const int b      = blockIdx.z >> 2;
    const int co0    = (blockIdx.z & 3) * 128;

    float acc[2][8][4];
#pragma unroll
    for (int mi = 0; mi < 2; ++mi)
#pragma unroll
        for (int ni = 0; ni < 8; ++ni)
#pragma unroll
            for (int q = 0; q < 4; ++q) acc[mi][ni][q] = 0.f;

    const float* inb = in + (size_t)b * Cin * PIX;
    const int groups = Cin >> 5;
    const int nsteps = groups * 9;

    // A-staging: co = (tid>>3) + 32*i, j4 = tid&7
    const int coA = tid >> 3;
    const int j4A = tid & 7;
    const uint32_t* wpA = wgt + coff9 + (size_t)(co0 + coA) * WCin9 + j4A * 4;

    // B-build: px = tid>>1, k-half = tid&1
    const int px_b = tid >> 1;
    const int kp_b = (tid & 1) * 8;
    const int pb   = (px_b >> 4) * 18 + (px_b & 15);

    // ldmatrix per-lane address offsets (bytes, within a tile)
    const int mm = lane >> 3, rr8 = lane & 7;
    const uint32_t aOff = (uint32_t)((mw + (mm & 1) * 8 + rr8) * 80 + (mm >> 1) * 16);
    const uint32_t bOff = (uint32_t)((nw + ((mm >> 1) & 1) * 8 + rr8) * 80 + (mm & 1) * 16);

    // prologue: prefetch weights for step 0
    uint4 wpre[4];
#pragma unroll
    for (int i = 0; i < 4; ++i)
        wpre[i] = *(const uint4*)(wpA + (size_t)(32 * i) * WCin9);

    int buf = 0;
    for (int grp = 0; grp < groups; ++grp) {
        // ---- stage input patch pre-split: 32 cin x 10 x 18 (zero halo) ----
        for (int idx = tid; idx < 32 * 180; idx += 256) {
            int c = idx / 180, rem = idx % 180;
            int pr = rem / 18, pc = rem % 18;
            int gh = tile_h - 1 + pr, gw = tile_w - 1 + pc;
            float v = 0.f;
            if ((unsigned)gh < 96u && (unsigned)gw < 96u)
                v = inb[(size_t)(grp * 32 + c) * PIX + gh * 96 + gw];
            sPatch[idx] = packsplit(v);
        }
        __syncthreads();   // patch ready; prev group fully consumed

#pragma unroll
        for (int c9 = 0; c9 < 9; ++c9) {
            uint32_t* sAh = (uint32_t*)(smem + CSM_TILES + buf * TILEB);
            uint32_t* sAl = (uint32_t*)(smem + CSM_TILES + (2 + buf) * TILEB);
            uint32_t* sBh = (uint32_t*)(smem + CSM_TILES + (4 + buf) * TILEB);
            uint32_t* sBl = (uint32_t*)(smem + CSM_TILES + (6 + buf) * TILEB);

            // ---- store prefetched A (pre-split) via byte_perm ----
            {
                const int d0 = coA * PADK + j4A * 2;
#pragma unroll
                for (int i = 0; i < 4; ++i) {
                    const uint4 w = wpre[i];
                    const int d = d0 + i * 32 * PADK;
                    sAh[d]     = __byte_perm(w.x, w.y, 0x5410);
                    sAh[d + 1] = __byte_perm(w.z, w.w, 0x5410);
                    sAl[d]     = __byte_perm(w.x, w.y, 0x7632);
                    sAl[d + 1] = __byte_perm(w.z, w.w, 0x7632);
                }
            }
            // ---- build B from packed patch ----
            {
                uint32_t hb[8], lb[8];
                if ((tid & 1) == 0) { BUILD_B_HALF(c9 * 32); }
                else                { BUILD_B_HALF(c9 * 32 + 16); }
                uint32_t* dh = sBh + px_b * PADK + kp_b;
                uint32_t* dl = sBl + px_b * PADK + kp_b;
                *(uint4*)(dh)     = make_uint4(hb[0], hb[1], hb[2], hb[3]);
                *(uint4*)(dh + 4) = make_uint4(hb[4], hb[5], hb[6], hb[7]);
                *(uint4*)(dl)     = make_uint4(lb[0], lb[1], lb[2], lb[3]);
                *(uint4*)(dl + 4) = make_uint4(lb[4], lb[5], lb[6], lb[7]);
            }
            // ---- prefetch weights for next chunk ----
            {
                const int nstep = grp * 9 + c9 + 1;
                if (nstep < nsteps) {
                    const uint32_t* wp = wpA + (size_t)nstep * 32;
#pragma unroll
                    for (int i = 0; i < 4; ++i)
                        wpre[i] = *(const uint4*)(wp + (size_t)(32 * i) * WCin9);
                }
            }
            __syncthreads();   // tiles[buf] ready

            const uint32_t tAh = sb + CSM_TILES + buf * TILEB;
            const uint32_t tAl = tAh + 2 * TILEB;
            const uint32_t tBh = tAh + 4 * TILEB;
            const uint32_t tBl = tAh + 6 * TILEB;

            // ---- compute: 2 k16-steps, ldmatrix fragments, 96 HMMA ----
#pragma unroll
            for (int ks = 0; ks < 2; ++ks) {
                const uint32_t kadd = ks * 32;
                uint32_t ah[2][4], al[2][4];
                LDSM_X4(ah[0][0], ah[0][1], ah[0][2], ah[0][3], tAh + aOff + kadd);
                LDSM_X4(ah[1][0], ah[1][1], ah[1][2], ah[1][3], tAh + aOff + 1280 + kadd);
                LDSM_X4(al[0][0], al[0][1], al[0][2], al[0][3], tAl + aOff + kadd);
                LDSM_X4(al[1][0], al[1][1], al[1][2], al[1][3], tAl + aOff + 1280 + kadd);
#pragma unroll
                for (int nip = 0; nip < 4; ++nip) {
                    uint32_t bh0, bh1, bh2, bh3, bl0, bl1, bl2, bl3;
                    LDSM_X4(bh0, bh1, bh2, bh3, tBh + bOff + nip * 1280 + kadd);
                    LDSM_X4(bl0, bl1, bl2, bl3, tBl + bOff + nip * 1280 + kadd);
                    const int ne = 2 * nip, no = 2 * nip + 1;
                    MMA_F16(acc[0][ne], ah[0], bh0, bh1);
                    MMA_F16(acc[1][ne], ah[1], bh0, bh1);
                    MMA_F16(acc[0][no], ah[0], bh2, bh3);
                    MMA_F16(acc[1][no], ah[1], bh2, bh3);
                    MMA_F16(acc[0][ne], ah[0], bl0, bl1);
                    MMA_F16(acc[1][ne], ah[1], bl0, bl1);
                    MMA_F16(acc[0][no], ah[0], bl2, bl3);
                    MMA_F16(acc[1][no], ah[1], bl2, bl3);
                    MMA_F16(acc[0][ne], al[0], bh0, bh1);
                    MMA_F16(acc[1][ne], al[1], bh0, bh1);
                    MMA_F16(acc[0][no], al[0], bh2, bh3);
                    MMA_F16(acc[1][no], al[1], bh2, bh3);
                }
            }
            buf ^= 1;
        }
    }

    // ---- epilogue: acc -> gmem (bn / relu / accumulate) ----
#pragma unroll
    for (int mi = 0; mi < 2; ++mi) {
#pragma unroll
        for (int rr = 0; rr < 2; ++rr) {
            int co = co0 + mw + mi * 16 + g + rr * 8;
            float s = 1.f, bs = 0.f;
            if (flags & 2) { s = scale[co]; bs = bias[co]; }
            const size_t obase = ((size_t)(b * 512 + co)) * PIX;
#pragma unroll
            for (int ni = 0; ni < 8; ++ni) {
#pragma unroll
                for (int cc = 0; cc < 2; ++cc) {
                    int px = nw + ni * 8 + 2 * tig + cc;
                    size_t oi = obase + (size_t)(tile_h + (px >> 4)) * 96
                              + tile_w + (px & 15);
                    float v = acc[mi][ni][rr * 2 + cc];
                    if (flags & 1) v += outp[oi];
                    v = v * s + bs;
                    if (flags & 4) v = fmaxf(v, 0.f);
                    outp[oi] = v;
                }
            }
        }
    }
}

// ---------------- fused q+k 1x1 projection (math identical to pw) ------------
__global__ void __launch_bounds__(256)
qk_kernel(const float* __restrict__ in, const float* __restrict__ qw,
          const float* __restrict__ kw, float* __restrict__ qo,
          float* __restrict__ ko)
{
    const int px0 = blockIdx.x * 128;
    const float* wgt = blockIdx.y ? kw : qw;
    float* out      = blockIdx.y ? ko : qo;
    const int b   = blockIdx.z;
    __shared__ float sIn[16][128];
    __shared__ float sW[64][17];
    const int tid = threadIdx.x, tx = tid & 15, ty = tid >> 4;
    float acc[4][8];
#pragma unroll
    for (int i = 0; i < 4; ++i)
#pragma unroll
        for (int r = 0; r < 8; ++r) acc[i][r] = 0.f;

    const float* inb = in + (size_t)b * CIX * PIX;
    for (int c0 = 0; c0 < CIX; c0 += 16) {
        __syncthreads();
#pragma unroll
        for (int k = 0; k < 8; ++k) {
            int idx = tid + k*256;
            sIn[idx >> 7][idx & 127] =
                inb[(size_t)(c0 + (idx >> 7)) * PIX + px0 + (idx & 127)];
        }
#pragma unroll
        for (int k = 0; k < 4; ++k) {
            int idx = tid + k*256;
            sW[idx >> 4][idx & 15] =
                wgt[(size_t)(idx >> 4) * CIX + c0 + (idx & 15)];
        }
        __syncthreads();
#pragma unroll
        for (int j = 0; j < 16; ++j) {
            float iv[8];
#pragma unroll
            for (int r = 0; r < 8; ++r) iv[r] = sIn[j][tx + 16*r];
#pragma unroll
            for (int i = 0; i < 4; ++i) {
                float wv = sW[ty*4 + i][j];
#pragma unroll
                for (int r = 0; r < 8; ++r)
                    acc[i][r] = fmaf(wv, iv[r], acc[i][r]);
            }
        }
    }
#pragma unroll
    for (int i = 0; i < 4; ++i)
#pragma unroll
        for (int r = 0; r < 8; ++r)
            out[((size_t)b*CQKX + ty*4 + i)*PIX + px0 + tx + 16*r] = acc[i][r];
}

// ---------------- v projection: 8co x 8px per thread (same k order) ----------
__global__ void __launch_bounds__(256)
pwv_kernel(const float* __restrict__ in, const float* __restrict__ wgt,
           float* __restrict__ out)
{
    const int px0 = blockIdx.x * 128;
    const int o0  = blockIdx.y * 128;
    const int b   = blockIdx.z;
    __shared__ float sIn[16][128];
    __shared__ float sW[128][17];
    const int tid = threadIdx.x, tx = tid & 15, ty = tid >> 4;
    float acc[8][8];
#pragma unroll
    for (int i = 0; i < 8; ++i)
#pragma unroll
        for (int r = 0; r < 8; ++r) acc[i][r] = 0.f;

    const float* inb = in + (size_t)b * CIX * PIX;
    for (int c0 = 0; c0 < CIX; c0 += 16) {
        __syncthreads();
#pragma unroll
        for (int k = 0; k < 8; ++k) {
            int idx = tid + k*256;
            sIn[idx >> 7][idx & 127] =
                inb[(size_t)(c0 + (idx >> 7)) * PIX + px0 + (idx & 127)];
        }
#pragma unroll
        for (int k = 0; k < 8; ++k) {
            int idx = tid + k*256;
            sW[idx >> 4][idx & 15] =
                wgt[(size_t)(o0 + (idx >> 4)) * CIX + c0 + (idx & 15)];
        }
        __syncthreads();
#pragma unroll
        for (int j = 0; j < 16; ++j) {
            float iv[8];
#pragma unroll
            for (int r = 0; r < 8; ++r) iv[r] = sIn[j][tx + 16*r];
#pragma unroll
            for (int i = 0; i < 8; ++i) {
                float wv = sW[ty*8 + i][j];
#pragma unroll
                for (int r = 0; r < 8; ++r)
                    acc[i][r] = fmaf(wv, iv[r], acc[i][r]);
            }
        }
    }
#pragma unroll
    for (int i = 0; i < 8; ++i)
#pragma unroll
        for (int r = 0; r < 8; ++r)
            out[((size_t)b*CIX + o0 + ty*8 + i)*PIX + px0 + tx + 16*r] = acc[i][r];
}

// ---------------- energies (unchanged) ---------------------------------------
__global__ void __launch_bounds__(256)
energyH_kernel(const float* __restrict__ q, const float* __restrict__ k,
               float* __restrict__ att)
{
    const int w = blockIdx.x, b = blockIdx.y;
    __shared__ float sQ[32][96], sK[32][96];
    const int tid = threadIdx.x;
    float acc[36];
#pragma unroll
    for (int i = 0; i < 36; ++i) acc[i] = 0.f;

    for (int c0 = 0; c0 < CQKX; c0 += 32) {
        __syncthreads();
        for (int idx = tid; idx < 32*96; idx += 256) {
            int c = idx / 96, p = idx % 96;
            size_t off = (size_t)(b*CQKX + c0 + c) * PIX + p*96 + w;
            sQ[c][p] = q[off];
            sK[c][p] = k[off];
        }
        __syncthreads();
#pragma unroll
        for (int it = 0; it < 36; ++it) {
            int oi = it*256 + tid;
            int h = oi / 96, gg = oi % 96;
            float s = acc[it];
#pragma unroll
            for (int c = 0; c < 32; ++c) s = fmaf(sQ[c][h], sK[c][gg], s);
            acc[it] = s;
        }
    }
#pragma unroll
    for (int it = 0; it < 36; ++it) {
        int oi = it*256 + tid;
        int h = oi / 96, gg = oi % 96;
        float vv = (gg == h) ? __int_as_float(0xff800000u) : acc[it];
        att[((size_t)((b*96 + h)*96 + w))*192 + gg] = vv;
    }
}

__global__ void __launch_bounds__(256)
energyW_kernel(const float* __restrict__ q, const float* __restrict__ k,
               float* __restrict__ att)
{
    const int h = blockIdx.x, b = blockIdx.y;
    __shared__ float sQ[32][96], sK[32][96];
    const int tid = threadIdx.x;
    float acc[36];
#pragma unroll
    for (int i = 0; i < 36; ++i) acc[i] = 0.f;

    for (int c0 = 0; c0 < CQKX; c0 += 32) {
        __syncthreads();
        for (int idx = tid; idx < 32*96; idx += 256) {
            int c = idx / 96, p = idx % 96;
            size_t off = (size_t)(b*CQKX + c0 + c) * PIX + h*96 + p;
            sQ[c][p] = q[off];
            sK[c][p] = k[off];
        }
        __syncthreads();
#pragma unroll
        for (int it = 0; it < 36; ++it) {
            int oi = it*256 + tid;
            int wc = oi / 96, v2 = oi % 96;
            float s = acc[it];
#pragma unroll
            for (int c = 0; c < 32; ++c) s = fmaf(sQ[c][wc], sK[c][v2], s);
            acc[it] = s;
        }
    }
#pragma unroll
    for (int it = 0; it < 36; ++it) {
        int oi = it*256 + tid;
        int wc = oi / 96, v2 = oi % 96;
        att[((size_t)((b*96 + h)*96 + wc))*192 + 96 + v2] = acc[it];
    }
}

// ---------------- softmax over 192 (unchanged) --------------------------------
__global__ void softmax_kernel(float* __restrict__ att)
{
    const int t = threadIdx.x;
    const size_t base = (size_t)blockIdx.x * 192;
    float v = att[base + t];
    __shared__ float red[6];

    float m = v;
#pragma unroll
    for (int o = 16; o; o >>= 1) m = fmaxf(m, __shfl_xor_sync(0xffffffffu, m, o));
    if ((t & 31) == 0) red[t >> 5] = m;
    __syncthreads();
    m = fmaxf(fmaxf(fmaxf(red[0], red[1]), fmaxf(red[2], red[3])),
              fmaxf(red[4], red[5]));

    float e = expf(v - m);
    float s = e;
#pragma unroll
    for (int o = 16; o; o >>= 1) s += __shfl_xor_sync(0xffffffffu, s, o);
    __syncthreads();
    if ((t & 31) == 0) red[t >> 5] = s;
    __syncthreads();
    s = red[0] + red[1] + red[2] + red[3] + red[4] + red[5];
    att[base + t] = e / s;
}

// ---------------- aggregation (unchanged) -------------------------------------
__global__ void __launch_bounds__(256)
aggH_kernel(const float* __restrict__ v, const float* __restrict__ att,
            const float* __restrict__ feat, const float* __restrict__ gp,
            float* __restrict__ dst)
{
    const int w = blockIdx.x, b = blockIdx.y;
    const int tid = threadIdx.x;
    __shared__ float sA2[96][97];
    __shared__ float sV[16][97];
    const float gm = *gp;

    for (int idx = tid; idx < 96*96; idx += 256) {
        int h = idx / 96, gg = idx % 96;
        sA2[h][gg] = att[((size_t)((b*96 + h)*96 + w))*192 + gg];
    }
    const int clg = tid >> 5;
    const int hq  = tid & 31;

    for (int c0 = 0; c0 < CIX; c0 += 16) {
        __syncthreads();
        for (int idx = tid; idx < 16*96; idx += 256) {
            int cl = idx / 96, gg = idx % 96;
            sV[cl][gg] = v[(size_t)(b*CIX + c0 + cl) * PIX + gg*96 + w];
        }
        __syncthreads();
        float a0[3] = {0.f,0.f,0.f}, a1[3] = {0.f,0.f,0.f};
#pragma unroll 4
        for (int gg = 0; gg < 96; ++gg) {
            float v0 = sV[clg*2][gg], v1 = sV[clg*2+1][gg];
#pragma unroll
            for (int r = 0; r < 3; ++r) {
                float a = sA2[hq + 32*r][gg];
                a0[r] = fmaf(v0, a, a0[r]);
                a1[r] = fmaf(v1, a, a1[r]);
            }
        }
#pragma unroll
        for (int r = 0; r < 3; ++r) {
            int h = hq + 32*r;
            size_t oi0 = ((size_t)(b*CIX + c0 + clg*2    )*96 + h)*96 + w;
            size_t oi1 = ((size_t)(b*CIX + c0 + clg*2 + 1)*96 + h)*96 + w;
            dst[oi0] = feat[oi0] + gm * a0[r];
            dst[oi1] = feat[oi1] + gm * a1[r];
        }
    }
}

__global__ void __launch_bounds__(256)
aggW_kernel(const float* __restrict__ v, const float* __restrict__ att,
            const float* __restrict__ gp, float* __restrict__ dst)
{
    const int h = blockIdx.x, b = blockIdx.y;
    const int tid = threadIdx.x;
    __shared__ float sA2[96][97];
    __shared__ float sV[16][97];
    const float gm = *gp;

    for (int idx = tid; idx < 96*96; idx += 256) {
        int wc = idx / 96, v2 = idx % 96;
        sA2[wc][v2] = att[((size_t)((b*96 + h)*96 + wc))*192 + 96 + v2];
    }
    const int clg = tid >> 5;
    const int wq  = tid & 31;

    for (int c0 = 0; c0 < CIX; c0 += 16) {
        __syncthreads();
        for (int idx = tid; idx < 16*96; idx += 256) {
            int cl = idx / 96, v2 = idx % 96;
            sV[cl][v2] = v[(size_t)(b*CIX + c0 + cl) * PIX + h*96 + v2];
        }
        __syncthreads();
        float a0[3] = {0.f,0.f,0.f}, a1[3] = {0.f,0.f,0.f};
#pragma unroll 4
        for (int v2 = 0; v2 < 96; ++v2) {
            float v0 = sV[clg*2][v2], v1 = sV[clg*2+1][v2];
#pragma unroll
            for (int r = 0; r < 3; ++r) {
                float a = sA2[wq + 32*r][v2];
                a0[r] = fmaf(v0, a, a0[r]);
                a1[r] = fmaf(v1, a, a1[r]);
            }
        }
#pragma unroll
        for (int r = 0; r < 3; ++r) {
            int wc = wq + 32*r;
            size_t oi0 = ((size_t)(b*CIX + c0 + clg*2    )*96 + h)*96 + wc;
            size_t oi1 = ((size_t)(b*CIX + c0 + clg*2 + 1)*96 + h)*96 + wc;
            dst[oi0] += gm * a0[r];
            dst[oi1] += gm * a1[r];
        }
    }
}

// ---------------- final 1x1 (unchanged) ---------------------------------------
__global__ void __launch_bounds__(256)
final_kernel(const float* __restrict__ in, const float* __restrict__ ow,
             const float* __restrict__ ob, float* __restrict__ out)
{
    const int px0 = blockIdx.x * 256;
    const int b   = blockIdx.y;
    const int tid = threadIdx.x;
    __shared__ float sIn[32][256];
    __shared__ float sW[19][32];
    float acc[NCL];
#pragma unroll
    for (int o = 0; o < NCL; ++o) acc[o] = 0.f;

    for (int c0 = 0; c0 < CIX; c0 += 32) {
        __syncthreads();
#pragma unroll
        for (int k = 0; k < 32; ++k)
            sIn[k][tid] = in[(size_t)(b*CIX + c0 + k) * PIX + px0 + tid];
        for (int idx = tid; idx < NCL*32; idx += 256)
            sW[idx >> 5][idx & 31] = ow[(size_t)(idx >> 5) * CIX + c0 + (idx & 31)];
        __syncthreads();
#pragma unroll
        for (int j = 0; j < 32; ++j) {
            float xv = sIn[j][tid];
#pragma unroll
            for (int o = 0; o < NCL; ++o) acc[o] = fmaf(sW[o][j], xv, acc[o]);
        }
    }
#pragma unroll
    for (int o = 0; o < NCL; ++o)
        out[((size_t)(b*NCL + o)) * PIX + px0 + tid] = acc[o] + ob[o];
}

// ---------------- launcher -----------------------------------------------------
extern "C" void kernel_launch(void* const* d_in, const int* in_sizes, int n_in,
                              void* d_out, int out_size)
{
    const float* x       = (const float*)d_in[0];
    const float* conva_w = (const float*)d_in[1];
    const float* bn1_s   = (const float*)d_in[2];
    const float* bn1_b   = (const float*)d_in[3];
    const float* q_w     = (const float*)d_in[4];
    const float* k_w     = (const float*)d_in[5];
    const float* v_w     = (const float*)d_in[6];
    const float* gamma   = (const float*)d_in[7];
    const float* convb_w = (const float*)d_in[8];
    const float* bn2_s   = (const float*)d_in[9];
    const float* bn2_b   = (const float*)d_in[10];
    const float* bott_w  = (const float*)d_in[11];
    const float* bn3_s   = (const float*)d_in[12];
    const float* bn3_b   = (const float*)d_in[13];
    const float* out_w   = (const float*)d_in[14];
    const float* out_b   = (const float*)d_in[15];
    float* out = (float*)d_out;

    float *pA, *pB, *pV, *pQ, *pK, *pAtt;
    uint32_t *pWa, *pWb, *pWt;
    cudaGetSymbolAddress((void**)&pA,   g_A);
    cudaGetSymbolAddress((void**)&pB,   g_Bf);
    cudaGetSymbolAddress((void**)&pV,   g_V);
    cudaGetSymbolAddress((void**)&pQ,   g_Q);
    cudaGetSymbolAddress((void**)&pK,   g_K);
    cudaGetSymbolAddress((void**)&pAtt, g_Att);
    cudaGetSymbolAddress((void**)&pWa,  g_Wa);
    cudaGetSymbolAddress((void**)&pWb,  g_Wb);
    cudaGetSymbolAddress((void**)&pWt,  g_Wt);

    cudaFuncSetAttribute(conv_tc_kernel,
                         cudaFuncAttributeMaxDynamicSharedMemorySize, CSM_TOTAL);

    const int nWa = CIX * CINX * 9;
    const int nWb = CIX * CIX * 9;
    const int nWt = CIX * (CINX + CIX) * 9;
    prep_w_kernel<<<(nWa + 255)/256, 256>>>(conva_w, pWa, nWa);
    prep_w_kernel<<<(nWb + 255)/256, 256>>>(convb_w, pWb, nWb);
    prep_w_kernel<<<(nWt + 255)/256, 256>>>(bott_w,  pWt, nWt);

    dim3 cgrid(6, 12, BB * (CIX/128));

    // conva + bn1 + relu -> A
    conv_tc_kernel<<<cgrid, 256, CSM_TOTAL>>>(x, pWa, bn1_s, bn1_b, pA,
                                              CINX, CINX*9, 0, 2|4);

    // 2 recurrences of criss-cross attention (fp32, proven)
    for (int r = 0; r < 2; ++r) {
        const float* feat = r ? pB : pA;
        float*       dst  = r ? pA : pB;
        qk_kernel<<<dim3(72, 2, BB), 256>>>(feat, q_w, k_w, pQ, pK);
        pwv_kernel<<<dim3(72, 4, BB), 256>>>(feat, v_w, pV);
        energyH_kernel<<<dim3(96, BB), 256>>>(pQ, pK, pAtt);
        energyW_kernel<<<dim3(96, BB), 256>>>(pQ, pK, pAtt);
        softmax_kernel<<<BB*PIX, 192>>>(pAtt);
        aggH_kernel<<<dim3(96, BB), 256>>>(pV, pAtt, feat, gamma, dst);
        aggW_kernel<<<dim3(96, BB), 256>>>(pV, pAtt, gamma, dst);
    }

    // convb + bn2 + relu : A -> B
    conv_tc_kernel<<<cgrid, 256, CSM_TOTAL>>>(pA, pWb, bn2_s, bn2_b, pB,
                                              CIX, CIX*9, 0, 2|4);

    // bottleneck conv over virtual concat [x (2048ch), B (512ch)] -> V, bn3
    conv_tc_kernel<<<cgrid, 256, CSM_TOTAL>>>(x,  pWt, nullptr, nullptr, pV,
                                              CINX, (CINX+CIX)*9, 0, 0);
    conv_tc_kernel<<<cgrid, 256, CSM_TOTAL>>>(pB, pWt, bn3_s, bn3_b, pV,
                                              CIX, (CINX+CIX)*9, CINX*9, 1|2);

    // final 1x1 -> d_out
    final_kernel<<<dim3(PIX/256, BB), 256>>>(pV, out_w, out_b, out);
}